// round 2
// baseline (speedup 1.0000x reference)
#include <cuda_runtime.h>
#include <math.h>

// Problem constants (from reference setup_inputs):
//   feat: [B=4, C=256, H=50, W=50] float32
//   rois: [R=128, 5] float32  (batch_idx, x1, y1, x2, y2)
//   out : [R, C, 7, 7] float32
#define CC 256
#define HH 50
#define WW 50
#define PP 7
#define SPATIAL_SCALE 0.0625f

__global__ void roipool_kernel(const float* __restrict__ feat,
                               const float* __restrict__ rois,
                               float* __restrict__ out,
                               int total) {
    int idx = blockIdx.x * blockDim.x + threadIdx.x;
    if (idx >= total) return;

    int pw = idx % PP;
    int ph = (idx / PP) % PP;
    int c  = (idx / (PP * PP)) % CC;
    int r  = idx / (PP * PP * CC);

    const float* rp = rois + (size_t)r * 5;
    int   b  = (int)rp[0];
    // jnp.round == round-half-to-even == rintf (RN mode); *0.0625 is exact.
    float x1 = rintf(rp[1] * SPATIAL_SCALE);
    float y1 = rintf(rp[2] * SPATIAL_SCALE);
    float x2 = rintf(rp[3] * SPATIAL_SCALE);
    float y2 = rintf(rp[4] * SPATIAL_SCALE);

    // XLA algebraic simplifier rewrites x/7 -> x * (1/7) with the reciprocal
    // constant-folded in f32. Replicate that EXACT op sequence: the 1-ulp
    // difference vs IEEE division flips ceil() at bin boundaries when the
    // ROI width is a multiple of 7 cells.
    const float INV7 = 1.0f / 7.0f;   // compile-time IEEE RN -> 0x3E124925
    float bw = __fmul_rn(fmaxf(x2 - x1 + 1.0f, 1.0f), INV7);
    float bh = __fmul_rn(fmaxf(y2 - y1 + 1.0f, 1.0f), INV7);

    float fpw = (float)pw;
    float fph = (float)ph;

    int ws = (int)fminf(fmaxf(floorf(__fmul_rn(bw, fpw))        + x1, 0.0f), (float)WW);
    int we = (int)fminf(fmaxf(ceilf (__fmul_rn(bw, fpw + 1.0f)) + x1, 0.0f), (float)WW);
    int hs = (int)fminf(fmaxf(floorf(__fmul_rn(bh, fph))        + y1, 0.0f), (float)HH);
    int he = (int)fminf(fmaxf(ceilf (__fmul_rn(bh, fph + 1.0f)) + y1, 0.0f), (float)HH);

    float m = -INFINITY;
    const float* fp = feat + ((size_t)b * CC + c) * (HH * WW);
    for (int h = hs; h < he; ++h) {
        const float* row = fp + h * WW;
        #pragma unroll 4
        for (int w = ws; w < we; ++w) {
            m = fmaxf(m, __ldg(row + w));
        }
    }
    // Empty bin -> -inf -> 0 (matches reference isneginf replacement)
    out[idx] = (m == -INFINITY) ? 0.0f : m;
}

extern "C" void kernel_launch(void* const* d_in, const int* in_sizes, int n_in,
                              void* d_out, int out_size) {
    const float* feat = (const float*)d_in[0];
    const float* rois = (const float*)d_in[1];
    float* out = (float*)d_out;

    int R = in_sizes[1] / 5;                 // 128
    int total = R * CC * PP * PP;            // 1,605,632

    int threads = 256;
    int blocks = (total + threads - 1) / threads;
    roipool_kernel<<<blocks, threads>>>(feat, rois, out, total);
}